// round 1
// baseline (speedup 1.0000x reference)
#include <cuda_runtime.h>
#include <cuda_bf16.h>

// Problem constants
#define S      2048
#define E      2048
#define HQ     32
#define HKV    8
#define D      64
// strides
#define QSTRIDE (HQ*D)    // 2048
#define KSTRIDE (HKV*D)   // 512

// ---------------- scratch (device globals; no allocation allowed) ----------
__device__ float g_Q[S * QSTRIDE];   // 16 MB
__device__ float g_K[S * KSTRIDE];   // 4 MB
__device__ float g_V[S * KSTRIDE];   // 4 MB
__device__ float g_A[S * QSTRIDE];   // 16 MB (attention output, [s, h*D+d])

// ---------------- generic fp32 tiled GEMM: C = A(MxK) * B(KxN) -------------
// 64x64 block tile, BK=16, 256 threads, 4x4 per thread.
__global__ void sgemm_kernel(const float* __restrict__ A,
                             const float* __restrict__ B,
                             float* __restrict__ C,
                             int M, int N, int K) {
    __shared__ float As[64][17];
    __shared__ float Bs[16][64];

    const int tid = threadIdx.x;
    const int ty = tid >> 4;          // 0..15
    const int tx = tid & 15;          // 0..15
    const int mbase = blockIdx.y * 64;
    const int nbase = blockIdx.x * 64;

    float acc[4][4];
#pragma unroll
    for (int i = 0; i < 4; ++i)
#pragma unroll
        for (int j = 0; j < 4; ++j) acc[i][j] = 0.f;

    for (int kb = 0; kb < K; kb += 16) {
        // load A tile 64x16
#pragma unroll
        for (int i = tid; i < 1024; i += 256) {
            int r = i >> 4, c = i & 15;
            As[r][c] = A[(size_t)(mbase + r) * K + kb + c];
        }
        // load B tile 16x64
#pragma unroll
        for (int i = tid; i < 1024; i += 256) {
            int r = i >> 6, c = i & 63;
            Bs[r][c] = B[(size_t)(kb + r) * N + nbase + c];
        }
        __syncthreads();

#pragma unroll
        for (int kk = 0; kk < 16; ++kk) {
            float a[4], b[4];
#pragma unroll
            for (int i = 0; i < 4; ++i) a[i] = As[ty * 4 + i][kk];
#pragma unroll
            for (int j = 0; j < 4; ++j) b[j] = Bs[kk][tx * 4 + j];
#pragma unroll
            for (int i = 0; i < 4; ++i)
#pragma unroll
                for (int j = 0; j < 4; ++j)
                    acc[i][j] = fmaf(a[i], b[j], acc[i][j]);
        }
        __syncthreads();
    }

#pragma unroll
    for (int i = 0; i < 4; ++i) {
        int row = mbase + ty * 4 + i;
#pragma unroll
        for (int j = 0; j < 4; ++j) {
            C[(size_t)row * N + nbase + tx * 4 + j] = acc[i][j];
        }
    }
}

// ---------------- RoPE: in-place on T [S, H, D] --------------------------
// freqs_cis is [S, D/2, 2] = F[s*64 + i*2 + {0,1}] (cos, sin)
__global__ void rope_kernel(float* __restrict__ T, const float* __restrict__ F,
                            int H, int rowStride) {
    int idx = blockIdx.x * blockDim.x + threadIdx.x;
    int total = S * H * (D / 2);
    if (idx >= total) return;
    int i = idx & 31;                 // freq pair index 0..31
    int h = (idx >> 5) % H;
    int s = idx / (32 * H);
    float fr = F[s * 64 + i * 2 + 0];
    float fi = F[s * 64 + i * 2 + 1];
    float* p = T + (size_t)s * rowStride + h * D + i * 2;
    float t0 = p[0], t1 = p[1];
    p[0] = t0 * fr - t1 * fi;
    p[1] = t0 * fi + t1 * fr;
}

// ---------------- flash attention (fp32, causal, GQA) ---------------------
// grid: (S/64, HQ), block: 256 threads (16x16), each thread owns 4x4 of the
// 64(q) x 64 tile. Online softmax with row stats in smem.
#define FA_PAD 65
#define FA_SMEM_FLOATS (3 * 64 * FA_PAD + 3 * 64)
#define FA_SMEM_BYTES  (FA_SMEM_FLOATS * 4)

__global__ void flash_kernel(const float* __restrict__ Q,
                             const float* __restrict__ Kg,
                             const float* __restrict__ Vg,
                             float* __restrict__ O) {
    const int h = blockIdx.y;
    const int qt = blockIdx.x;
    const int qbase = qt * 64;
    const int kh = h >> 2;            // GQA: 4 query heads per kv head

    extern __shared__ float sm[];
    float* Qs  = sm;                        // 64 x 65
    float* KVs = sm + 64 * FA_PAD;          // 64 x 65 (K tile, then reused for V)
    float* Ss  = sm + 2 * 64 * FA_PAD;      // 64 x 65
    float* mrow = sm + 3 * 64 * FA_PAD;     // 64
    float* lrow = mrow + 64;                // 64
    float* frow = lrow + 64;                // 64

    const int tid = threadIdx.x;
    const int ty = tid >> 4, tx = tid & 15;
    const int r0 = ty * 4, c0 = tx * 4;

    // load Q tile
#pragma unroll
    for (int i = tid; i < 4096; i += 256) {
        int r = i >> 6, c = i & 63;
        Qs[r * FA_PAD + c] = Q[(size_t)(qbase + r) * QSTRIDE + h * D + c];
    }
    if (tid < 64) { mrow[tid] = -1e30f; lrow[tid] = 0.f; }

    float acc[4][4];
#pragma unroll
    for (int i = 0; i < 4; ++i)
#pragma unroll
        for (int j = 0; j < 4; ++j) acc[i][j] = 0.f;

    __syncthreads();

    for (int kt = 0; kt <= qt; ++kt) {
        const int kbase = kt * 64;

        // load K tile
#pragma unroll
        for (int i = tid; i < 4096; i += 256) {
            int r = i >> 6, c = i & 63;
            KVs[r * FA_PAD + c] = Kg[(size_t)(kbase + r) * KSTRIDE + kh * D + c];
        }
        __syncthreads();

        // S = Q K^T * scale (+ causal mask on diagonal tile)
        float s4[4][4];
#pragma unroll
        for (int i = 0; i < 4; ++i)
#pragma unroll
            for (int j = 0; j < 4; ++j) s4[i][j] = 0.f;

#pragma unroll 8
        for (int kk = 0; kk < 64; ++kk) {
            float a[4], b[4];
#pragma unroll
            for (int i = 0; i < 4; ++i) a[i] = Qs[(r0 + i) * FA_PAD + kk];
#pragma unroll
            for (int j = 0; j < 4; ++j) b[j] = KVs[(c0 + j) * FA_PAD + kk];
#pragma unroll
            for (int i = 0; i < 4; ++i)
#pragma unroll
                for (int j = 0; j < 4; ++j)
                    s4[i][j] = fmaf(a[i], b[j], s4[i][j]);
        }

        const float scale = 0.125f;   // 1/sqrt(64)
        const bool diag = (kt == qt);
#pragma unroll
        for (int i = 0; i < 4; ++i) {
#pragma unroll
            for (int j = 0; j < 4; ++j) {
                float v = s4[i][j] * scale;
                if (diag && (kbase + c0 + j) > (qbase + r0 + i)) v = -1e30f;
                Ss[(r0 + i) * FA_PAD + c0 + j] = v;
            }
        }
        __syncthreads();

        // overlap: load V tile over the K buffer; threads<64 also do row pass
#pragma unroll
        for (int i = tid; i < 4096; i += 256) {
            int r = i >> 6, c = i & 63;
            KVs[r * FA_PAD + c] = Vg[(size_t)(kbase + r) * KSTRIDE + kh * D + c];
        }
        if (tid < 64) {
            const int r = tid;
            float mold = mrow[r];
            float mx = mold;
#pragma unroll 8
            for (int c = 0; c < 64; ++c) mx = fmaxf(mx, Ss[r * FA_PAD + c]);
            float fac = __expf(mold - mx);
            float sum = 0.f;
#pragma unroll 8
            for (int c = 0; c < 64; ++c) {
                float p = __expf(Ss[r * FA_PAD + c] - mx);
                Ss[r * FA_PAD + c] = p;
                sum += p;
            }
            lrow[r] = lrow[r] * fac + sum;
            mrow[r] = mx;
            frow[r] = fac;
        }
        __syncthreads();

        // rescale accumulators and accumulate O += P @ V
        float f[4];
#pragma unroll
        for (int i = 0; i < 4; ++i) f[i] = frow[r0 + i];
#pragma unroll
        for (int i = 0; i < 4; ++i)
#pragma unroll
            for (int j = 0; j < 4; ++j) acc[i][j] *= f[i];

#pragma unroll 8
        for (int kk = 0; kk < 64; ++kk) {
            float p[4], v[4];
#pragma unroll
            for (int i = 0; i < 4; ++i) p[i] = Ss[(r0 + i) * FA_PAD + kk];
#pragma unroll
            for (int j = 0; j < 4; ++j) v[j] = KVs[kk * FA_PAD + c0 + j];
#pragma unroll
            for (int i = 0; i < 4; ++i)
#pragma unroll
                for (int j = 0; j < 4; ++j)
                    acc[i][j] = fmaf(p[i], v[j], acc[i][j]);
        }
        __syncthreads();  // before next iteration overwrites KVs / Ss
    }

    // normalize and write out: O[q, h*D + d]
#pragma unroll
    for (int i = 0; i < 4; ++i) {
        float inv_l = 1.f / lrow[r0 + i];
        int row = qbase + r0 + i;
#pragma unroll
        for (int j = 0; j < 4; ++j) {
            O[(size_t)row * QSTRIDE + h * D + c0 + j] = acc[i][j] * inv_l;
        }
    }
}

// ---------------- launch ---------------------------------------------------
extern "C" void kernel_launch(void* const* d_in, const int* in_sizes, int n_in,
                              void* d_out, int out_size) {
    const float* x  = (const float*)d_in[0];
    const float* fc = (const float*)d_in[1];
    // d_in[2] = mask (unused; causal mask applied analytically)
    const float* Wq = (const float*)d_in[3];
    const float* Wk = (const float*)d_in[4];
    const float* Wv = (const float*)d_in[5];
    const float* Wo = (const float*)d_in[6];
    float* out = (float*)d_out;

    float *Q, *K, *V, *A;
    cudaGetSymbolAddress((void**)&Q, g_Q);
    cudaGetSymbolAddress((void**)&K, g_K);
    cudaGetSymbolAddress((void**)&V, g_V);
    cudaGetSymbolAddress((void**)&A, g_A);

    cudaFuncSetAttribute(flash_kernel,
                         cudaFuncAttributeMaxDynamicSharedMemorySize,
                         FA_SMEM_BYTES);

    // QKV projections
    sgemm_kernel<<<dim3(E / 64, S / 64), 256>>>(x, Wq, Q, S, E, E);
    sgemm_kernel<<<dim3(KSTRIDE / 64, S / 64), 256>>>(x, Wk, K, S, KSTRIDE, E);
    sgemm_kernel<<<dim3(KSTRIDE / 64, S / 64), 256>>>(x, Wv, V, S, KSTRIDE, E);

    // RoPE on Q and K
    rope_kernel<<<(S * HQ * (D / 2) + 255) / 256, 256>>>(Q, fc, HQ, QSTRIDE);
    rope_kernel<<<(S * HKV * (D / 2) + 255) / 256, 256>>>(K, fc, HKV, KSTRIDE);

    // causal GQA flash attention
    flash_kernel<<<dim3(S / 64, HQ), 256, FA_SMEM_BYTES>>>(Q, K, V, A);

    // output projection
    sgemm_kernel<<<dim3(E / 64, S / 64), 256>>>(A, Wo, out, S, E, E);
}

// round 2
// speedup vs baseline: 2.9313x; 2.9313x over previous
#include <cuda_runtime.h>
#include <cuda_bf16.h>

// Problem constants
#define S      2048
#define E      2048
#define HQ     32
#define HKV    8
#define D      64
#define QSTRIDE (HQ*D)    // 2048
#define KSTRIDE (HKV*D)   // 512

// ---------------- scratch (device globals; no allocation allowed) ----------
__device__ float g_Q[S * QSTRIDE];   // 16 MB
__device__ float g_K[S * KSTRIDE];   // 4 MB
__device__ float g_V[S * KSTRIDE];   // 4 MB
__device__ float g_A[S * QSTRIDE];   // 16 MB

// ---------------- helpers ---------------------------------------------------
__device__ __forceinline__ unsigned f2t(float f) {
    unsigned u;
    asm("cvt.rna.tf32.f32 %0, %1;" : "=r"(u) : "f"(f));
    return u;
}

__device__ __forceinline__ void mma_tf32(float c[4],
                                         unsigned a0, unsigned a1, unsigned a2, unsigned a3,
                                         unsigned b0, unsigned b1) {
    asm volatile(
        "mma.sync.aligned.m16n8k8.row.col.f32.tf32.tf32.f32 "
        "{%0,%1,%2,%3}, {%4,%5,%6,%7}, {%8,%9}, {%0,%1,%2,%3};\n"
        : "+f"(c[0]), "+f"(c[1]), "+f"(c[2]), "+f"(c[3])
        : "r"(a0), "r"(a1), "r"(a2), "r"(a3), "r"(b0), "r"(b1));
}

// ---------------- TF32 tensor-core GEMM: C = A(MxK) * B(KxN), row-major ----
// Block tile 128x128, BK=32, 256 threads (8 warps, 4x2), warp tile 32x64.
__global__ void tgemm_kernel(const float* __restrict__ A,
                             const float* __restrict__ B,
                             float* __restrict__ C,
                             int M, int N, int K) {
    __shared__ unsigned As[32][136];   // [k][m], pitch 136 -> conflict-free frags
    __shared__ unsigned Bs[32][136];   // [k][n]

    const int tid  = threadIdx.x;
    const int lane = tid & 31;
    const int warp = tid >> 5;
    const int wm = warp >> 1;          // 0..3
    const int wn = warp & 1;           // 0..1
    const int m0w = wm * 32;
    const int n0w = wn * 64;
    const int mbase = blockIdx.y * 128;
    const int nbase = blockIdx.x * 128;

    float acc[2][8][4];
#pragma unroll
    for (int mt = 0; mt < 2; ++mt)
#pragma unroll
        for (int nt = 0; nt < 8; ++nt)
#pragma unroll
            for (int j = 0; j < 4; ++j) acc[mt][nt][j] = 0.f;

    const int arow = tid >> 3, af4 = tid & 7;        // A loads: 128 rows x 8 f4
    const int brow = tid >> 5, bf4 = tid & 31;       // B loads: 32 rows x 32 f4

    for (int kb = 0; kb < K; kb += 32) {
        // load A tile (128 x 32), store transposed [k][m]
#pragma unroll
        for (int i = 0; i < 4; ++i) {
            int r = arow + i * 32;
            float4 v = *(const float4*)&A[(size_t)(mbase + r) * K + kb + af4 * 4];
            As[af4 * 4 + 0][r] = f2t(v.x);
            As[af4 * 4 + 1][r] = f2t(v.y);
            As[af4 * 4 + 2][r] = f2t(v.z);
            As[af4 * 4 + 3][r] = f2t(v.w);
        }
        // load B tile (32 x 128), store [k][n]
#pragma unroll
        for (int i = 0; i < 4; ++i) {
            int r = brow + i * 8;
            float4 v = *(const float4*)&B[(size_t)(kb + r) * N + nbase + bf4 * 4];
            uint4 u = make_uint4(f2t(v.x), f2t(v.y), f2t(v.z), f2t(v.w));
            *(uint4*)&Bs[r][bf4 * 4] = u;
        }
        __syncthreads();

#pragma unroll
        for (int ks = 0; ks < 4; ++ks) {
            const int k0 = ks * 8;
            unsigned a[2][4];
#pragma unroll
            for (int mt = 0; mt < 2; ++mt) {
                int m = m0w + mt * 16;
                a[mt][0] = As[k0 + (lane & 3)][m + (lane >> 2)];
                a[mt][1] = As[k0 + (lane & 3)][m + 8 + (lane >> 2)];
                a[mt][2] = As[k0 + 4 + (lane & 3)][m + (lane >> 2)];
                a[mt][3] = As[k0 + 4 + (lane & 3)][m + 8 + (lane >> 2)];
            }
#pragma unroll
            for (int nt = 0; nt < 8; ++nt) {
                int n = n0w + nt * 8;
                unsigned b0 = Bs[k0 + (lane & 3)][n + (lane >> 2)];
                unsigned b1 = Bs[k0 + 4 + (lane & 3)][n + (lane >> 2)];
                mma_tf32(acc[0][nt], a[0][0], a[0][1], a[0][2], a[0][3], b0, b1);
                mma_tf32(acc[1][nt], a[1][0], a[1][1], a[1][2], a[1][3], b0, b1);
            }
        }
        __syncthreads();
    }

    // epilogue
#pragma unroll
    for (int mt = 0; mt < 2; ++mt) {
#pragma unroll
        for (int nt = 0; nt < 8; ++nt) {
            int row = mbase + m0w + mt * 16 + (lane >> 2);
            int col = nbase + n0w + nt * 8 + 2 * (lane & 3);
            *(float2*)&C[(size_t)row * N + col] = make_float2(acc[mt][nt][0], acc[mt][nt][1]);
            *(float2*)&C[(size_t)(row + 8) * N + col] = make_float2(acc[mt][nt][2], acc[mt][nt][3]);
        }
    }
}

// ---------------- RoPE: in-place on T [S, H, D] ----------------------------
__global__ void rope_kernel(float* __restrict__ T, const float* __restrict__ F,
                            int H, int rowStride) {
    int idx = blockIdx.x * blockDim.x + threadIdx.x;
    int total = S * H * (D / 2);
    if (idx >= total) return;
    int i = idx & 31;
    int h = (idx >> 5) % H;
    int s = idx / (32 * H);
    float fr = F[s * 64 + i * 2 + 0];
    float fi = F[s * 64 + i * 2 + 1];
    float* p = T + (size_t)s * rowStride + h * D + i * 2;
    float t0 = p[0], t1 = p[1];
    p[0] = t0 * fr - t1 * fi;
    p[1] = t0 * fi + t1 * fr;
}

// ---------------- TF32 tensor-core flash attention (causal, GQA) -----------
// grid (S/64, HQ), 128 threads (4 warps). Warp w owns q rows [16w,16w+16).
// Online softmax in registers with quad shuffles; P re-fragmented via smem.
#define FP 68   // smem pitch (floats); 68 % 32 == 4 -> conflict-free frag loads
#define FA_SMEM_BYTES (4 * 64 * FP * 4)

__global__ void flash_tc_kernel(const float* __restrict__ Q,
                                const float* __restrict__ Kg,
                                const float* __restrict__ Vg,
                                float* __restrict__ O) {
    const int h = blockIdx.y;
    const int qt = blockIdx.x;
    const int qbase = qt * 64;
    const int kh = h >> 2;

    extern __shared__ unsigned smu[];
    unsigned* Qs = smu;                 // [64][FP]  (q rows x d), tf32
    unsigned* Ks = smu + 64 * FP;       // [64][FP]  (k rows x d)
    unsigned* Vs = smu + 2 * 64 * FP;   // [64][FP]  (d x k rows) TRANSPOSED
    unsigned* Ps = smu + 3 * 64 * FP;   // [64][FP]  (q rows x k cols)

    const int tid = threadIdx.x;
    const int lane = tid & 31;
    const int warp = tid >> 5;
    const int m0 = warp * 16;
    const int qr = lane >> 2;           // 0..7
    const int qc = lane & 3;            // 0..3

    const int f4 = tid & 15;            // 16 float4 per 64-col row
    const int row0 = tid >> 4;          // 0..7

    // load Q tile (once)
#pragma unroll
    for (int i = 0; i < 8; ++i) {
        int r = row0 + i * 8;
        float4 v = *(const float4*)&Q[(size_t)(qbase + r) * QSTRIDE + h * D + f4 * 4];
        uint4 u = make_uint4(f2t(v.x), f2t(v.y), f2t(v.z), f2t(v.w));
        *(uint4*)&Qs[r * FP + f4 * 4] = u;
    }

    float o[8][4];
#pragma unroll
    for (int nt = 0; nt < 8; ++nt)
#pragma unroll
        for (int j = 0; j < 4; ++j) o[nt][j] = 0.f;
    float m_lo = -1e30f, m_hi = -1e30f, l_lo = 0.f, l_hi = 0.f;

    for (int kt = 0; kt <= qt; ++kt) {
        __syncthreads();   // previous iteration's reads of Ks/Vs complete
        const int kbase = kt * 64;

        // load K tile [kr][d]
#pragma unroll
        for (int i = 0; i < 8; ++i) {
            int r = row0 + i * 8;
            float4 v = *(const float4*)&Kg[(size_t)(kbase + r) * KSTRIDE + kh * D + f4 * 4];
            uint4 u = make_uint4(f2t(v.x), f2t(v.y), f2t(v.z), f2t(v.w));
            *(uint4*)&Ks[r * FP + f4 * 4] = u;
        }
        // load V tile transposed: Vs[d][kr]
#pragma unroll
        for (int i = 0; i < 8; ++i) {
            int r = row0 + i * 8;
            float4 v = *(const float4*)&Vg[(size_t)(kbase + r) * KSTRIDE + kh * D + f4 * 4];
            Vs[(f4 * 4 + 0) * FP + r] = f2t(v.x);
            Vs[(f4 * 4 + 1) * FP + r] = f2t(v.y);
            Vs[(f4 * 4 + 2) * FP + r] = f2t(v.z);
            Vs[(f4 * 4 + 3) * FP + r] = f2t(v.w);
        }
        __syncthreads();

        // ---- S = Q K^T ----
        float s[8][4];
#pragma unroll
        for (int nt = 0; nt < 8; ++nt)
#pragma unroll
            for (int j = 0; j < 4; ++j) s[nt][j] = 0.f;

#pragma unroll
        for (int ks = 0; ks < 8; ++ks) {
            const int k0 = ks * 8;
            unsigned a0 = Qs[(m0 + qr) * FP + k0 + qc];
            unsigned a1 = Qs[(m0 + 8 + qr) * FP + k0 + qc];
            unsigned a2 = Qs[(m0 + qr) * FP + k0 + 4 + qc];
            unsigned a3 = Qs[(m0 + 8 + qr) * FP + k0 + 4 + qc];
#pragma unroll
            for (int nt = 0; nt < 8; ++nt) {
                unsigned b0 = Ks[(nt * 8 + qr) * FP + k0 + qc];
                unsigned b1 = Ks[(nt * 8 + qr) * FP + k0 + 4 + qc];
                mma_tf32(s[nt], a0, a1, a2, a3, b0, b1);
            }
        }

        // ---- scale + causal mask ----
        const bool diag = (kt == qt);
        const int q_lo = qbase + m0 + qr;
        const int q_hi = q_lo + 8;
#pragma unroll
        for (int nt = 0; nt < 8; ++nt) {
#pragma unroll
            for (int j = 0; j < 2; ++j) {
                int kcol = kbase + nt * 8 + 2 * qc + j;
                float v0 = s[nt][j] * 0.125f;
                float v1 = s[nt][2 + j] * 0.125f;
                if (diag && kcol > q_lo) v0 = -1e30f;
                if (diag && kcol > q_hi) v1 = -1e30f;
                s[nt][j] = v0;
                s[nt][2 + j] = v1;
            }
        }

        // ---- online softmax (register, quad reductions) ----
        float tm_lo = -1e30f, tm_hi = -1e30f;
#pragma unroll
        for (int nt = 0; nt < 8; ++nt) {
            tm_lo = fmaxf(tm_lo, fmaxf(s[nt][0], s[nt][1]));
            tm_hi = fmaxf(tm_hi, fmaxf(s[nt][2], s[nt][3]));
        }
#pragma unroll
        for (int off = 1; off <= 2; off <<= 1) {
            tm_lo = fmaxf(tm_lo, __shfl_xor_sync(0xffffffffu, tm_lo, off));
            tm_hi = fmaxf(tm_hi, __shfl_xor_sync(0xffffffffu, tm_hi, off));
        }
        float mn_lo = fmaxf(m_lo, tm_lo);
        float mn_hi = fmaxf(m_hi, tm_hi);
        float fac_lo = __expf(m_lo - mn_lo);
        float fac_hi = __expf(m_hi - mn_hi);

        float sum_lo = 0.f, sum_hi = 0.f;
#pragma unroll
        for (int nt = 0; nt < 8; ++nt) {
            float p0 = __expf(s[nt][0] - mn_lo);
            float p1 = __expf(s[nt][1] - mn_lo);
            float p2 = __expf(s[nt][2] - mn_hi);
            float p3 = __expf(s[nt][3] - mn_hi);
            s[nt][0] = p0; s[nt][1] = p1; s[nt][2] = p2; s[nt][3] = p3;
            sum_lo += p0 + p1;
            sum_hi += p2 + p3;
        }
#pragma unroll
        for (int off = 1; off <= 2; off <<= 1) {
            sum_lo += __shfl_xor_sync(0xffffffffu, sum_lo, off);
            sum_hi += __shfl_xor_sync(0xffffffffu, sum_hi, off);
        }
        l_lo = l_lo * fac_lo + sum_lo;
        l_hi = l_hi * fac_hi + sum_hi;
        m_lo = mn_lo;
        m_hi = mn_hi;

#pragma unroll
        for (int nt = 0; nt < 8; ++nt) {
            o[nt][0] *= fac_lo; o[nt][1] *= fac_lo;
            o[nt][2] *= fac_hi; o[nt][3] *= fac_hi;
        }

        // ---- write P fragments to smem (warp-private rows) ----
#pragma unroll
        for (int nt = 0; nt < 8; ++nt) {
            int r = m0 + qr;
            int c = nt * 8 + 2 * qc;
            Ps[r * FP + c]         = f2t(s[nt][0]);
            Ps[r * FP + c + 1]     = f2t(s[nt][1]);
            Ps[(r + 8) * FP + c]     = f2t(s[nt][2]);
            Ps[(r + 8) * FP + c + 1] = f2t(s[nt][3]);
        }
        __syncwarp();

        // ---- O += P V ----
#pragma unroll
        for (int ks = 0; ks < 8; ++ks) {
            const int k0 = ks * 8;
            unsigned a0 = Ps[(m0 + qr) * FP + k0 + qc];
            unsigned a1 = Ps[(m0 + 8 + qr) * FP + k0 + qc];
            unsigned a2 = Ps[(m0 + qr) * FP + k0 + 4 + qc];
            unsigned a3 = Ps[(m0 + 8 + qr) * FP + k0 + 4 + qc];
#pragma unroll
            for (int nt = 0; nt < 8; ++nt) {
                unsigned b0 = Vs[(nt * 8 + qr) * FP + k0 + qc];
                unsigned b1 = Vs[(nt * 8 + qr) * FP + k0 + 4 + qc];
                mma_tf32(o[nt], a0, a1, a2, a3, b0, b1);
            }
        }
    }

    // ---- normalize + write out ----
    float inv_lo = 1.f / l_lo;
    float inv_hi = 1.f / l_hi;
#pragma unroll
    for (int nt = 0; nt < 8; ++nt) {
        int row = qbase + m0 + qr;
        int col = h * D + nt * 8 + 2 * qc;
        *(float2*)&O[(size_t)row * QSTRIDE + col] =
            make_float2(o[nt][0] * inv_lo, o[nt][1] * inv_lo);
        *(float2*)&O[(size_t)(row + 8) * QSTRIDE + col] =
            make_float2(o[nt][2] * inv_hi, o[nt][3] * inv_hi);
    }
}

// ---------------- launch ---------------------------------------------------
extern "C" void kernel_launch(void* const* d_in, const int* in_sizes, int n_in,
                              void* d_out, int out_size) {
    const float* x  = (const float*)d_in[0];
    const float* fc = (const float*)d_in[1];
    const float* Wq = (const float*)d_in[3];
    const float* Wk = (const float*)d_in[4];
    const float* Wv = (const float*)d_in[5];
    const float* Wo = (const float*)d_in[6];
    float* out = (float*)d_out;

    float *Q, *K, *V, *A;
    cudaGetSymbolAddress((void**)&Q, g_Q);
    cudaGetSymbolAddress((void**)&K, g_K);
    cudaGetSymbolAddress((void**)&V, g_V);
    cudaGetSymbolAddress((void**)&A, g_A);

    cudaFuncSetAttribute(flash_tc_kernel,
                         cudaFuncAttributeMaxDynamicSharedMemorySize,
                         FA_SMEM_BYTES);

    // QKV projections (TF32 tensor cores)
    tgemm_kernel<<<dim3(E / 128, S / 128), 256>>>(x, Wq, Q, S, E, E);
    tgemm_kernel<<<dim3(KSTRIDE / 128, S / 128), 256>>>(x, Wk, K, S, KSTRIDE, E);
    tgemm_kernel<<<dim3(KSTRIDE / 128, S / 128), 256>>>(x, Wv, V, S, KSTRIDE, E);

    // RoPE on Q and K
    rope_kernel<<<(S * HQ * (D / 2) + 255) / 256, 256>>>(Q, fc, HQ, QSTRIDE);
    rope_kernel<<<(S * HKV * (D / 2) + 255) / 256, 256>>>(K, fc, HKV, KSTRIDE);

    // causal GQA flash attention (TF32 tensor cores)
    flash_tc_kernel<<<dim3(S / 64, HQ), 128, FA_SMEM_BYTES>>>(Q, K, V, A);

    // output projection
    tgemm_kernel<<<dim3(E / 128, S / 128), 256>>>(A, Wo, out, S, E, E);
}

// round 3
// speedup vs baseline: 3.7253x; 1.2709x over previous
#include <cuda_runtime.h>
#include <cuda_bf16.h>

// Problem constants
#define S      2048
#define E      2048
#define HQ     32
#define HKV    8
#define D      64
#define QSTRIDE (HQ*D)    // 2048
#define KSTRIDE (HKV*D)   // 512
#define NTOT   (QSTRIDE + 2*KSTRIDE)  // 3072 fused QKV columns

// ---------------- scratch (device globals; no allocation allowed) ----------
__device__ float g_Q[S * QSTRIDE];   // 16 MB
__device__ float g_K[S * KSTRIDE];   // 4 MB
__device__ float g_V[S * KSTRIDE];   // 4 MB
__device__ float g_A[S * QSTRIDE];   // 16 MB

// ---------------- helpers ---------------------------------------------------
__device__ __forceinline__ unsigned f2t(float f) {
    unsigned u;
    asm("cvt.rna.tf32.f32 %0, %1;" : "=r"(u) : "f"(f));
    return u;
}

__device__ __forceinline__ void mma_tf32(float c[4],
                                         unsigned a0, unsigned a1, unsigned a2, unsigned a3,
                                         unsigned b0, unsigned b1) {
    asm volatile(
        "mma.sync.aligned.m16n8k8.row.col.f32.tf32.tf32.f32 "
        "{%0,%1,%2,%3}, {%4,%5,%6,%7}, {%8,%9}, {%0,%1,%2,%3};\n"
        : "+f"(c[0]), "+f"(c[1]), "+f"(c[2]), "+f"(c[3])
        : "r"(a0), "r"(a1), "r"(a2), "r"(a3), "r"(b0), "r"(b1));
}

// ============================================================================
// Fused QKV projection GEMM + RoPE epilogue.
// C[2048 x 3072] where cols [0,2048) -> Q (rope), [2048,2560) -> K (rope),
// [2560,3072) -> V (no rope). Block tile 128x128, BK=32, 256 threads,
// register-prefetch double buffering.
// ============================================================================
__global__ void qkv_gemm_kernel(const float* __restrict__ A,
                                const float* __restrict__ Wq,
                                const float* __restrict__ Wk,
                                const float* __restrict__ Wv,
                                const float* __restrict__ F,
                                float* __restrict__ Qp,
                                float* __restrict__ Kp,
                                float* __restrict__ Vp) {
    __shared__ unsigned As[32][136];
    __shared__ unsigned Bs[32][136];

    const int K = E;
    const int tid  = threadIdx.x;
    const int lane = tid & 31;
    const int warp = tid >> 5;
    const int wm = warp >> 1;
    const int wn = warp & 1;
    const int m0w = wm * 32;
    const int n0w = wn * 64;
    const int mbase = blockIdx.y * 128;
    const int nbase = blockIdx.x * 128;

    // region select (tile-uniform; boundaries are multiples of 128)
    const float* Bsrc; float* Csrc; int Nb; int colbase; bool rope;
    if (nbase < QSTRIDE)            { Bsrc = Wq; Csrc = Qp; Nb = QSTRIDE; colbase = nbase;              rope = true;  }
    else if (nbase < QSTRIDE + KSTRIDE) { Bsrc = Wk; Csrc = Kp; Nb = KSTRIDE; colbase = nbase - QSTRIDE;     rope = true;  }
    else                            { Bsrc = Wv; Csrc = Vp; Nb = KSTRIDE; colbase = nbase - QSTRIDE - KSTRIDE; rope = false; }

    float acc[2][8][4];
#pragma unroll
    for (int mt = 0; mt < 2; ++mt)
#pragma unroll
        for (int nt = 0; nt < 8; ++nt)
#pragma unroll
            for (int j = 0; j < 4; ++j) acc[mt][nt][j] = 0.f;

    const int arow = tid >> 3, af4 = tid & 7;
    const int brow = tid >> 5, bf4 = tid & 31;

    float4 pa[4], pb[4];
#pragma unroll
    for (int i = 0; i < 4; ++i)
        pa[i] = *(const float4*)&A[(size_t)(mbase + arow + i * 32) * K + af4 * 4];
#pragma unroll
    for (int i = 0; i < 4; ++i)
        pb[i] = *(const float4*)&Bsrc[(size_t)(brow + i * 8) * Nb + colbase + bf4 * 4];

    for (int kb = 0; kb < K; kb += 32) {
        // store prefetched tiles to smem (convert to tf32)
#pragma unroll
        for (int i = 0; i < 4; ++i) {
            int r = arow + i * 32;
            As[af4 * 4 + 0][r] = f2t(pa[i].x);
            As[af4 * 4 + 1][r] = f2t(pa[i].y);
            As[af4 * 4 + 2][r] = f2t(pa[i].z);
            As[af4 * 4 + 3][r] = f2t(pa[i].w);
        }
#pragma unroll
        for (int i = 0; i < 4; ++i) {
            int r = brow + i * 8;
            uint4 u = make_uint4(f2t(pb[i].x), f2t(pb[i].y), f2t(pb[i].z), f2t(pb[i].w));
            *(uint4*)&Bs[r][bf4 * 4] = u;
        }
        __syncthreads();

        if (kb + 32 < K) {
#pragma unroll
            for (int i = 0; i < 4; ++i)
                pa[i] = *(const float4*)&A[(size_t)(mbase + arow + i * 32) * K + kb + 32 + af4 * 4];
#pragma unroll
            for (int i = 0; i < 4; ++i)
                pb[i] = *(const float4*)&Bsrc[(size_t)(kb + 32 + brow + i * 8) * Nb + colbase + bf4 * 4];
        }

#pragma unroll
        for (int ks = 0; ks < 4; ++ks) {
            const int k0 = ks * 8;
            unsigned a[2][4];
#pragma unroll
            for (int mt = 0; mt < 2; ++mt) {
                int m = m0w + mt * 16;
                a[mt][0] = As[k0 + (lane & 3)][m + (lane >> 2)];
                a[mt][1] = As[k0 + (lane & 3)][m + 8 + (lane >> 2)];
                a[mt][2] = As[k0 + 4 + (lane & 3)][m + (lane >> 2)];
                a[mt][3] = As[k0 + 4 + (lane & 3)][m + 8 + (lane >> 2)];
            }
#pragma unroll
            for (int nt = 0; nt < 8; ++nt) {
                int n = n0w + nt * 8;
                unsigned b0 = Bs[k0 + (lane & 3)][n + (lane >> 2)];
                unsigned b1 = Bs[k0 + 4 + (lane & 3)][n + (lane >> 2)];
                mma_tf32(acc[0][nt], a[0][0], a[0][1], a[0][2], a[0][3], b0, b1);
                mma_tf32(acc[1][nt], a[1][0], a[1][1], a[1][2], a[1][3], b0, b1);
            }
        }
        __syncthreads();
    }

    // epilogue with optional fused RoPE (cols come in rotation pairs (2c,2c+1))
#pragma unroll
    for (int mt = 0; mt < 2; ++mt) {
#pragma unroll
        for (int nt = 0; nt < 8; ++nt) {
            int row = mbase + m0w + mt * 16 + (lane >> 2);
            int colg = n0w + nt * 8 + 2 * (lane & 3);      // even
            int lcol = colbase + colg;                      // col within dest matrix
            float2 v0 = make_float2(acc[mt][nt][0], acc[mt][nt][1]);
            float2 v1 = make_float2(acc[mt][nt][2], acc[mt][nt][3]);
            if (rope) {
                int d = lcol & 63;                          // even dim index in head
                float2 f0 = *(const float2*)&F[(size_t)row * 64 + d];
                float2 f1 = *(const float2*)&F[(size_t)(row + 8) * 64 + d];
                v0 = make_float2(v0.x * f0.x - v0.y * f0.y, v0.x * f0.y + v0.y * f0.x);
                v1 = make_float2(v1.x * f1.x - v1.y * f1.y, v1.x * f1.y + v1.y * f1.x);
            }
            *(float2*)&Csrc[(size_t)row * Nb + lcol] = v0;
            *(float2*)&Csrc[(size_t)(row + 8) * Nb + lcol] = v1;
        }
    }
}

// ============================================================================
// Plain TF32 GEMM (for output projection): C = A(MxK) B(KxN), double-buffered.
// ============================================================================
__global__ void tgemm_kernel(const float* __restrict__ A,
                             const float* __restrict__ B,
                             float* __restrict__ C,
                             int M, int N, int K) {
    __shared__ unsigned As[32][136];
    __shared__ unsigned Bs[32][136];

    const int tid  = threadIdx.x;
    const int lane = tid & 31;
    const int warp = tid >> 5;
    const int wm = warp >> 1;
    const int wn = warp & 1;
    const int m0w = wm * 32;
    const int n0w = wn * 64;
    const int mbase = blockIdx.y * 128;
    const int nbase = blockIdx.x * 128;

    float acc[2][8][4];
#pragma unroll
    for (int mt = 0; mt < 2; ++mt)
#pragma unroll
        for (int nt = 0; nt < 8; ++nt)
#pragma unroll
            for (int j = 0; j < 4; ++j) acc[mt][nt][j] = 0.f;

    const int arow = tid >> 3, af4 = tid & 7;
    const int brow = tid >> 5, bf4 = tid & 31;

    float4 pa[4], pb[4];
#pragma unroll
    for (int i = 0; i < 4; ++i)
        pa[i] = *(const float4*)&A[(size_t)(mbase + arow + i * 32) * K + af4 * 4];
#pragma unroll
    for (int i = 0; i < 4; ++i)
        pb[i] = *(const float4*)&B[(size_t)(brow + i * 8) * N + nbase + bf4 * 4];

    for (int kb = 0; kb < K; kb += 32) {
#pragma unroll
        for (int i = 0; i < 4; ++i) {
            int r = arow + i * 32;
            As[af4 * 4 + 0][r] = f2t(pa[i].x);
            As[af4 * 4 + 1][r] = f2t(pa[i].y);
            As[af4 * 4 + 2][r] = f2t(pa[i].z);
            As[af4 * 4 + 3][r] = f2t(pa[i].w);
        }
#pragma unroll
        for (int i = 0; i < 4; ++i) {
            int r = brow + i * 8;
            uint4 u = make_uint4(f2t(pb[i].x), f2t(pb[i].y), f2t(pb[i].z), f2t(pb[i].w));
            *(uint4*)&Bs[r][bf4 * 4] = u;
        }
        __syncthreads();

        if (kb + 32 < K) {
#pragma unroll
            for (int i = 0; i < 4; ++i)
                pa[i] = *(const float4*)&A[(size_t)(mbase + arow + i * 32) * K + kb + 32 + af4 * 4];
#pragma unroll
            for (int i = 0; i < 4; ++i)
                pb[i] = *(const float4*)&B[(size_t)(kb + 32 + brow + i * 8) * N + nbase + bf4 * 4];
        }

#pragma unroll
        for (int ks = 0; ks < 4; ++ks) {
            const int k0 = ks * 8;
            unsigned a[2][4];
#pragma unroll
            for (int mt = 0; mt < 2; ++mt) {
                int m = m0w + mt * 16;
                a[mt][0] = As[k0 + (lane & 3)][m + (lane >> 2)];
                a[mt][1] = As[k0 + (lane & 3)][m + 8 + (lane >> 2)];
                a[mt][2] = As[k0 + 4 + (lane & 3)][m + (lane >> 2)];
                a[mt][3] = As[k0 + 4 + (lane & 3)][m + 8 + (lane >> 2)];
            }
#pragma unroll
            for (int nt = 0; nt < 8; ++nt) {
                int n = n0w + nt * 8;
                unsigned b0 = Bs[k0 + (lane & 3)][n + (lane >> 2)];
                unsigned b1 = Bs[k0 + 4 + (lane & 3)][n + (lane >> 2)];
                mma_tf32(acc[0][nt], a[0][0], a[0][1], a[0][2], a[0][3], b0, b1);
                mma_tf32(acc[1][nt], a[1][0], a[1][1], a[1][2], a[1][3], b0, b1);
            }
        }
        __syncthreads();
    }

#pragma unroll
    for (int mt = 0; mt < 2; ++mt) {
#pragma unroll
        for (int nt = 0; nt < 8; ++nt) {
            int row = mbase + m0w + mt * 16 + (lane >> 2);
            int col = nbase + n0w + nt * 8 + 2 * (lane & 3);
            *(float2*)&C[(size_t)row * N + col] = make_float2(acc[mt][nt][0], acc[mt][nt][1]);
            *(float2*)&C[(size_t)(row + 8) * N + col] = make_float2(acc[mt][nt][2], acc[mt][nt][3]);
        }
    }
}

// ============================================================================
// TF32 flash attention, causal, GQA. Q tile = 128 rows, KV tile = 64.
// 256 threads (8 warps); warp w owns q rows [16w, 16w+16).
// ============================================================================
#define FP 68
#define FA_SMEM_BYTES ((128 + 64 + 64 + 128) * FP * 4)   // Qs,Ks,Vs,Ps

__global__ void flash_tc_kernel(const float* __restrict__ Q,
                                const float* __restrict__ Kg,
                                const float* __restrict__ Vg,
                                float* __restrict__ O) {
    const int h = blockIdx.y;
    const int qt = (gridDim.x - 1) - blockIdx.x;   // heavy tiles first
    const int qbase = qt * 128;
    const int kh = h >> 2;

    extern __shared__ unsigned smu[];
    unsigned* Qs = smu;                   // [128][FP]
    unsigned* Ks = smu + 128 * FP;        // [64][FP]
    unsigned* Vs = smu + 192 * FP;        // [64][FP] transposed (d x k)
    unsigned* Ps = smu + 256 * FP;        // [128][FP]

    const int tid = threadIdx.x;
    const int lane = tid & 31;
    const int warp = tid >> 5;
    const int m0 = warp * 16;
    const int qr = lane >> 2;
    const int qc = lane & 3;

    const int f4 = tid & 15;
    const int row0 = tid >> 4;            // 0..15

    // load Q tile (128 x 64)
#pragma unroll
    for (int i = 0; i < 8; ++i) {
        int r = row0 + i * 16;
        float4 v = *(const float4*)&Q[(size_t)(qbase + r) * QSTRIDE + h * D + f4 * 4];
        uint4 u = make_uint4(f2t(v.x), f2t(v.y), f2t(v.z), f2t(v.w));
        *(uint4*)&Qs[r * FP + f4 * 4] = u;
    }

    float o[8][4];
#pragma unroll
    for (int nt = 0; nt < 8; ++nt)
#pragma unroll
        for (int j = 0; j < 4; ++j) o[nt][j] = 0.f;
    float m_lo = -1e30f, m_hi = -1e30f, l_lo = 0.f, l_hi = 0.f;

    const int kt_max = 2 * qt + 1;        // inclusive
    for (int kt = 0; kt <= kt_max; ++kt) {
        __syncthreads();
        const int kbase = kt * 64;

        // load K tile (64 x 64)
#pragma unroll
        for (int i = 0; i < 4; ++i) {
            int r = row0 + i * 16;
            float4 v = *(const float4*)&Kg[(size_t)(kbase + r) * KSTRIDE + kh * D + f4 * 4];
            uint4 u = make_uint4(f2t(v.x), f2t(v.y), f2t(v.z), f2t(v.w));
            *(uint4*)&Ks[r * FP + f4 * 4] = u;
        }
        // load V tile transposed (d x 64)
#pragma unroll
        for (int i = 0; i < 4; ++i) {
            int r = row0 + i * 16;
            float4 v = *(const float4*)&Vg[(size_t)(kbase + r) * KSTRIDE + kh * D + f4 * 4];
            Vs[(f4 * 4 + 0) * FP + r] = f2t(v.x);
            Vs[(f4 * 4 + 1) * FP + r] = f2t(v.y);
            Vs[(f4 * 4 + 2) * FP + r] = f2t(v.z);
            Vs[(f4 * 4 + 3) * FP + r] = f2t(v.w);
        }
        __syncthreads();

        // warps whose rows are entirely below this k tile skip compute
        const bool active = (kbase <= qbase + m0 + 15);
        if (!active) continue;

        // ---- S = Q K^T ----
        float s[8][4];
#pragma unroll
        for (int nt = 0; nt < 8; ++nt)
#pragma unroll
            for (int j = 0; j < 4; ++j) s[nt][j] = 0.f;

#pragma unroll
        for (int ks = 0; ks < 8; ++ks) {
            const int k0 = ks * 8;
            unsigned a0 = Qs[(m0 + qr) * FP + k0 + qc];
            unsigned a1 = Qs[(m0 + 8 + qr) * FP + k0 + qc];
            unsigned a2 = Qs[(m0 + qr) * FP + k0 + 4 + qc];
            unsigned a3 = Qs[(m0 + 8 + qr) * FP + k0 + 4 + qc];
#pragma unroll
            for (int nt = 0; nt < 8; ++nt) {
                unsigned b0 = Ks[(nt * 8 + qr) * FP + k0 + qc];
                unsigned b1 = Ks[(nt * 8 + qr) * FP + k0 + 4 + qc];
                mma_tf32(s[nt], a0, a1, a2, a3, b0, b1);
            }
        }

        // ---- scale + causal mask ----
        const int q_lo = qbase + m0 + qr;
        const int q_hi = q_lo + 8;
        const bool need_mask = (kbase + 63 > q_lo);   // per-thread
#pragma unroll
        for (int nt = 0; nt < 8; ++nt) {
#pragma unroll
            for (int j = 0; j < 2; ++j) {
                int kcol = kbase + nt * 8 + 2 * qc + j;
                float v0 = s[nt][j] * 0.125f;
                float v1 = s[nt][2 + j] * 0.125f;
                if (need_mask && kcol > q_lo) v0 = -1e30f;
                if (need_mask && kcol > q_hi) v1 = -1e30f;
                s[nt][j] = v0;
                s[nt][2 + j] = v1;
            }
        }

        // ---- online softmax (quad reductions) ----
        float tm_lo = -1e30f, tm_hi = -1e30f;
#pragma unroll
        for (int nt = 0; nt < 8; ++nt) {
            tm_lo = fmaxf(tm_lo, fmaxf(s[nt][0], s[nt][1]));
            tm_hi = fmaxf(tm_hi, fmaxf(s[nt][2], s[nt][3]));
        }
#pragma unroll
        for (int off = 1; off <= 2; off <<= 1) {
            tm_lo = fmaxf(tm_lo, __shfl_xor_sync(0xffffffffu, tm_lo, off));
            tm_hi = fmaxf(tm_hi, __shfl_xor_sync(0xffffffffu, tm_hi, off));
        }
        float mn_lo = fmaxf(m_lo, tm_lo);
        float mn_hi = fmaxf(m_hi, tm_hi);
        float fac_lo = __expf(m_lo - mn_lo);
        float fac_hi = __expf(m_hi - mn_hi);

        float sum_lo = 0.f, sum_hi = 0.f;
#pragma unroll
        for (int nt = 0; nt < 8; ++nt) {
            float p0 = __expf(s[nt][0] - mn_lo);
            float p1 = __expf(s[nt][1] - mn_lo);
            float p2 = __expf(s[nt][2] - mn_hi);
            float p3 = __expf(s[nt][3] - mn_hi);
            s[nt][0] = p0; s[nt][1] = p1; s[nt][2] = p2; s[nt][3] = p3;
            sum_lo += p0 + p1;
            sum_hi += p2 + p3;
        }
#pragma unroll
        for (int off = 1; off <= 2; off <<= 1) {
            sum_lo += __shfl_xor_sync(0xffffffffu, sum_lo, off);
            sum_hi += __shfl_xor_sync(0xffffffffu, sum_hi, off);
        }
        l_lo = l_lo * fac_lo + sum_lo;
        l_hi = l_hi * fac_hi + sum_hi;
        m_lo = mn_lo;
        m_hi = mn_hi;

#pragma unroll
        for (int nt = 0; nt < 8; ++nt) {
            o[nt][0] *= fac_lo; o[nt][1] *= fac_lo;
            o[nt][2] *= fac_hi; o[nt][3] *= fac_hi;
        }

        // ---- write P fragments to smem (warp-private rows) ----
#pragma unroll
        for (int nt = 0; nt < 8; ++nt) {
            int r = m0 + qr;
            int c = nt * 8 + 2 * qc;
            Ps[r * FP + c]           = f2t(s[nt][0]);
            Ps[r * FP + c + 1]       = f2t(s[nt][1]);
            Ps[(r + 8) * FP + c]     = f2t(s[nt][2]);
            Ps[(r + 8) * FP + c + 1] = f2t(s[nt][3]);
        }
        __syncwarp();

        // ---- O += P V ----
#pragma unroll
        for (int ks = 0; ks < 8; ++ks) {
            const int k0 = ks * 8;
            unsigned a0 = Ps[(m0 + qr) * FP + k0 + qc];
            unsigned a1 = Ps[(m0 + 8 + qr) * FP + k0 + qc];
            unsigned a2 = Ps[(m0 + qr) * FP + k0 + 4 + qc];
            unsigned a3 = Ps[(m0 + 8 + qr) * FP + k0 + 4 + qc];
#pragma unroll
            for (int nt = 0; nt < 8; ++nt) {
                unsigned b0 = Vs[(nt * 8 + qr) * FP + k0 + qc];
                unsigned b1 = Vs[(nt * 8 + qr) * FP + k0 + 4 + qc];
                mma_tf32(o[nt], a0, a1, a2, a3, b0, b1);
            }
        }
    }

    // ---- normalize + write out ----
    float inv_lo = 1.f / l_lo;
    float inv_hi = 1.f / l_hi;
#pragma unroll
    for (int nt = 0; nt < 8; ++nt) {
        int row = qbase + m0 + qr;
        int col = h * D + nt * 8 + 2 * qc;
        *(float2*)&O[(size_t)row * QSTRIDE + col] =
            make_float2(o[nt][0] * inv_lo, o[nt][1] * inv_lo);
        *(float2*)&O[(size_t)(row + 8) * QSTRIDE + col] =
            make_float2(o[nt][2] * inv_hi, o[nt][3] * inv_hi);
    }
}

// ---------------- launch ---------------------------------------------------
extern "C" void kernel_launch(void* const* d_in, const int* in_sizes, int n_in,
                              void* d_out, int out_size) {
    const float* x  = (const float*)d_in[0];
    const float* fc = (const float*)d_in[1];
    const float* Wq = (const float*)d_in[3];
    const float* Wk = (const float*)d_in[4];
    const float* Wv = (const float*)d_in[5];
    const float* Wo = (const float*)d_in[6];
    float* out = (float*)d_out;

    float *Q, *K, *V, *A;
    cudaGetSymbolAddress((void**)&Q, g_Q);
    cudaGetSymbolAddress((void**)&K, g_K);
    cudaGetSymbolAddress((void**)&V, g_V);
    cudaGetSymbolAddress((void**)&A, g_A);

    cudaFuncSetAttribute(flash_tc_kernel,
                         cudaFuncAttributeMaxDynamicSharedMemorySize,
                         FA_SMEM_BYTES);

    // fused QKV projection + RoPE
    qkv_gemm_kernel<<<dim3(NTOT / 128, S / 128), 256>>>(x, Wq, Wk, Wv, fc, Q, K, V);

    // causal GQA flash attention (TF32 tensor cores), 128-row q tiles
    flash_tc_kernel<<<dim3(S / 128, HQ), 256, FA_SMEM_BYTES>>>(Q, K, V, A);

    // output projection
    tgemm_kernel<<<dim3(E / 128, S / 128), 256>>>(A, Wo, out, S, E, E);
}

// round 4
// speedup vs baseline: 3.9646x; 1.0642x over previous
#include <cuda_runtime.h>
#include <cuda_bf16.h>

// Problem constants
#define S      2048
#define E      2048
#define HQ     32
#define HKV    8
#define D      64
#define QSTRIDE (HQ*D)    // 2048
#define KSTRIDE (HKV*D)   // 512
#define NTOT   (QSTRIDE + 2*KSTRIDE)  // 3072

// ---------------- scratch (device globals; no allocation allowed) ----------
__device__ float g_Q[S * QSTRIDE];
__device__ float g_K[S * KSTRIDE];
__device__ float g_V[S * KSTRIDE];
__device__ float g_A[S * QSTRIDE];

// ---------------- helpers ---------------------------------------------------
__device__ __forceinline__ unsigned f2t(float f) {
    unsigned u;
    asm("cvt.rna.tf32.f32 %0, %1;" : "=r"(u) : "f"(f));
    return u;
}

__device__ __forceinline__ void mma_tf32(float c[4],
                                         unsigned a0, unsigned a1, unsigned a2, unsigned a3,
                                         unsigned b0, unsigned b1) {
    asm volatile(
        "mma.sync.aligned.m16n8k8.row.col.f32.tf32.tf32.f32 "
        "{%0,%1,%2,%3}, {%4,%5,%6,%7}, {%8,%9}, {%0,%1,%2,%3};\n"
        : "+f"(c[0]), "+f"(c[1]), "+f"(c[2]), "+f"(c[3])
        : "r"(a0), "r"(a1), "r"(a2), "r"(a3), "r"(b0), "r"(b1));
}

// ============================================================================
// Fused QKV GEMM + RoPE epilogue. 128 threads / 4 warps, block 128x128,
// warp tile 64x64 (mt=4, nt=8), BK=32, register-prefetch double buffer.
// ============================================================================
__global__ __launch_bounds__(128)
void qkv_gemm_kernel(const float* __restrict__ A,
                     const float* __restrict__ Wq,
                     const float* __restrict__ Wk,
                     const float* __restrict__ Wv,
                     const float* __restrict__ F,
                     float* __restrict__ Qp,
                     float* __restrict__ Kp,
                     float* __restrict__ Vp) {
    __shared__ unsigned As[32][136];
    __shared__ unsigned Bs[32][136];

    const int K = E;
    const int tid  = threadIdx.x;
    const int lane = tid & 31;
    const int warp = tid >> 5;          // 0..3
    const int wm = warp >> 1;
    const int wn = warp & 1;
    const int m0w = wm * 64;
    const int n0w = wn * 64;
    const int mbase = blockIdx.y * 128;
    const int nbase = blockIdx.x * 128;
    const int qr = lane >> 2, qc = lane & 3;

    const float* Bsrc; float* Csrc; int Nb; int colbase; bool rope;
    if (nbase < QSTRIDE)                { Bsrc = Wq; Csrc = Qp; Nb = QSTRIDE; colbase = nbase;                     rope = true;  }
    else if (nbase < QSTRIDE + KSTRIDE) { Bsrc = Wk; Csrc = Kp; Nb = KSTRIDE; colbase = nbase - QSTRIDE;           rope = true;  }
    else                                { Bsrc = Wv; Csrc = Vp; Nb = KSTRIDE; colbase = nbase - QSTRIDE - KSTRIDE; rope = false; }

    float acc[4][8][4];
#pragma unroll
    for (int mt = 0; mt < 4; ++mt)
#pragma unroll
        for (int nt = 0; nt < 8; ++nt)
#pragma unroll
            for (int j = 0; j < 4; ++j) acc[mt][nt][j] = 0.f;

    const int arow = tid >> 3, af4 = tid & 7;     // A: 128 rows x 8 f4
    const int brow = tid >> 5, bf4 = tid & 31;    // B: 32 rows x 32 f4

    float4 pa[8], pb[8];
#pragma unroll
    for (int i = 0; i < 8; ++i)
        pa[i] = *(const float4*)&A[(size_t)(mbase + arow + i * 16) * K + af4 * 4];
#pragma unroll
    for (int i = 0; i < 8; ++i)
        pb[i] = *(const float4*)&Bsrc[(size_t)(brow + i * 4) * Nb + colbase + bf4 * 4];

    for (int kb = 0; kb < K; kb += 32) {
#pragma unroll
        for (int i = 0; i < 8; ++i) {
            int r = arow + i * 16;
            As[af4 * 4 + 0][r] = f2t(pa[i].x);
            As[af4 * 4 + 1][r] = f2t(pa[i].y);
            As[af4 * 4 + 2][r] = f2t(pa[i].z);
            As[af4 * 4 + 3][r] = f2t(pa[i].w);
        }
#pragma unroll
        for (int i = 0; i < 8; ++i) {
            int r = brow + i * 4;
            uint4 u = make_uint4(f2t(pb[i].x), f2t(pb[i].y), f2t(pb[i].z), f2t(pb[i].w));
            *(uint4*)&Bs[r][bf4 * 4] = u;
        }
        __syncthreads();

        if (kb + 32 < K) {
#pragma unroll
            for (int i = 0; i < 8; ++i)
                pa[i] = *(const float4*)&A[(size_t)(mbase + arow + i * 16) * K + kb + 32 + af4 * 4];
#pragma unroll
            for (int i = 0; i < 8; ++i)
                pb[i] = *(const float4*)&Bsrc[(size_t)(kb + 32 + brow + i * 4) * Nb + colbase + bf4 * 4];
        }

#pragma unroll
        for (int ks = 0; ks < 4; ++ks) {
            const int k0 = ks * 8;
            unsigned a[4][4];
#pragma unroll
            for (int mt = 0; mt < 4; ++mt) {
                int m = m0w + mt * 16;
                a[mt][0] = As[k0 + qc][m + qr];
                a[mt][1] = As[k0 + qc][m + 8 + qr];
                a[mt][2] = As[k0 + 4 + qc][m + qr];
                a[mt][3] = As[k0 + 4 + qc][m + 8 + qr];
            }
#pragma unroll
            for (int nt = 0; nt < 8; ++nt) {
                int n = n0w + nt * 8;
                unsigned b0 = Bs[k0 + qc][n + qr];
                unsigned b1 = Bs[k0 + 4 + qc][n + qr];
#pragma unroll
                for (int mt = 0; mt < 4; ++mt)
                    mma_tf32(acc[mt][nt], a[mt][0], a[mt][1], a[mt][2], a[mt][3], b0, b1);
            }
        }
        __syncthreads();
    }

    // epilogue with fused RoPE (cols in rotation pairs (2c, 2c+1))
#pragma unroll
    for (int mt = 0; mt < 4; ++mt) {
#pragma unroll
        for (int nt = 0; nt < 8; ++nt) {
            int row = mbase + m0w + mt * 16 + qr;
            int lcol = colbase + n0w + nt * 8 + 2 * qc;
            float2 v0 = make_float2(acc[mt][nt][0], acc[mt][nt][1]);
            float2 v1 = make_float2(acc[mt][nt][2], acc[mt][nt][3]);
            if (rope) {
                int d = lcol & 63;
                float2 f0 = *(const float2*)&F[(size_t)row * 64 + d];
                float2 f1 = *(const float2*)&F[(size_t)(row + 8) * 64 + d];
                v0 = make_float2(v0.x * f0.x - v0.y * f0.y, v0.x * f0.y + v0.y * f0.x);
                v1 = make_float2(v1.x * f1.x - v1.y * f1.y, v1.x * f1.y + v1.y * f1.x);
            }
            *(float2*)&Csrc[(size_t)row * Nb + lcol] = v0;
            *(float2*)&Csrc[(size_t)(row + 8) * Nb + lcol] = v1;
        }
    }
}

// ============================================================================
// Plain TF32 GEMM (output projection), same 64x64-warp-tile structure.
// ============================================================================
__global__ __launch_bounds__(128)
void tgemm_kernel(const float* __restrict__ A,
                  const float* __restrict__ B,
                  float* __restrict__ C,
                  int M, int N, int K) {
    __shared__ unsigned As[32][136];
    __shared__ unsigned Bs[32][136];

    const int tid  = threadIdx.x;
    const int lane = tid & 31;
    const int warp = tid >> 5;
    const int wm = warp >> 1;
    const int wn = warp & 1;
    const int m0w = wm * 64;
    const int n0w = wn * 64;
    const int mbase = blockIdx.y * 128;
    const int nbase = blockIdx.x * 128;
    const int qr = lane >> 2, qc = lane & 3;

    float acc[4][8][4];
#pragma unroll
    for (int mt = 0; mt < 4; ++mt)
#pragma unroll
        for (int nt = 0; nt < 8; ++nt)
#pragma unroll
            for (int j = 0; j < 4; ++j) acc[mt][nt][j] = 0.f;

    const int arow = tid >> 3, af4 = tid & 7;
    const int brow = tid >> 5, bf4 = tid & 31;

    float4 pa[8], pb[8];
#pragma unroll
    for (int i = 0; i < 8; ++i)
        pa[i] = *(const float4*)&A[(size_t)(mbase + arow + i * 16) * K + af4 * 4];
#pragma unroll
    for (int i = 0; i < 8; ++i)
        pb[i] = *(const float4*)&B[(size_t)(brow + i * 4) * N + nbase + bf4 * 4];

    for (int kb = 0; kb < K; kb += 32) {
#pragma unroll
        for (int i = 0; i < 8; ++i) {
            int r = arow + i * 16;
            As[af4 * 4 + 0][r] = f2t(pa[i].x);
            As[af4 * 4 + 1][r] = f2t(pa[i].y);
            As[af4 * 4 + 2][r] = f2t(pa[i].z);
            As[af4 * 4 + 3][r] = f2t(pa[i].w);
        }
#pragma unroll
        for (int i = 0; i < 8; ++i) {
            int r = brow + i * 4;
            uint4 u = make_uint4(f2t(pb[i].x), f2t(pb[i].y), f2t(pb[i].z), f2t(pb[i].w));
            *(uint4*)&Bs[r][bf4 * 4] = u;
        }
        __syncthreads();

        if (kb + 32 < K) {
#pragma unroll
            for (int i = 0; i < 8; ++i)
                pa[i] = *(const float4*)&A[(size_t)(mbase + arow + i * 16) * K + kb + 32 + af4 * 4];
#pragma unroll
            for (int i = 0; i < 8; ++i)
                pb[i] = *(const float4*)&B[(size_t)(kb + 32 + brow + i * 4) * N + nbase + bf4 * 4];
        }

#pragma unroll
        for (int ks = 0; ks < 4; ++ks) {
            const int k0 = ks * 8;
            unsigned a[4][4];
#pragma unroll
            for (int mt = 0; mt < 4; ++mt) {
                int m = m0w + mt * 16;
                a[mt][0] = As[k0 + qc][m + qr];
                a[mt][1] = As[k0 + qc][m + 8 + qr];
                a[mt][2] = As[k0 + 4 + qc][m + qr];
                a[mt][3] = As[k0 + 4 + qc][m + 8 + qr];
            }
#pragma unroll
            for (int nt = 0; nt < 8; ++nt) {
                int n = n0w + nt * 8;
                unsigned b0 = Bs[k0 + qc][n + qr];
                unsigned b1 = Bs[k0 + 4 + qc][n + qr];
#pragma unroll
                for (int mt = 0; mt < 4; ++mt)
                    mma_tf32(acc[mt][nt], a[mt][0], a[mt][1], a[mt][2], a[mt][3], b0, b1);
            }
        }
        __syncthreads();
    }

#pragma unroll
    for (int mt = 0; mt < 4; ++mt) {
#pragma unroll
        for (int nt = 0; nt < 8; ++nt) {
            int row = mbase + m0w + mt * 16 + qr;
            int col = nbase + n0w + nt * 8 + 2 * qc;
            *(float2*)&C[(size_t)row * N + col] = make_float2(acc[mt][nt][0], acc[mt][nt][1]);
            *(float2*)&C[(size_t)(row + 8) * N + col] = make_float2(acc[mt][nt][2], acc[mt][nt][3]);
        }
    }
}

// ============================================================================
// TF32 flash attention, causal, GQA (unchanged from R2).
// ============================================================================
#define FP 68
#define FA_SMEM_BYTES ((128 + 64 + 64 + 128) * FP * 4)

__global__ void flash_tc_kernel(const float* __restrict__ Q,
                                const float* __restrict__ Kg,
                                const float* __restrict__ Vg,
                                float* __restrict__ O) {
    const int h = blockIdx.y;
    const int qt = (gridDim.x - 1) - blockIdx.x;
    const int qbase = qt * 128;
    const int kh = h >> 2;

    extern __shared__ unsigned smu[];
    unsigned* Qs = smu;
    unsigned* Ks = smu + 128 * FP;
    unsigned* Vs = smu + 192 * FP;
    unsigned* Ps = smu + 256 * FP;

    const int tid = threadIdx.x;
    const int lane = tid & 31;
    const int warp = tid >> 5;
    const int m0 = warp * 16;
    const int qr = lane >> 2;
    const int qc = lane & 3;

    const int f4 = tid & 15;
    const int row0 = tid >> 4;

#pragma unroll
    for (int i = 0; i < 8; ++i) {
        int r = row0 + i * 16;
        float4 v = *(const float4*)&Q[(size_t)(qbase + r) * QSTRIDE + h * D + f4 * 4];
        uint4 u = make_uint4(f2t(v.x), f2t(v.y), f2t(v.z), f2t(v.w));
        *(uint4*)&Qs[r * FP + f4 * 4] = u;
    }

    float o[8][4];
#pragma unroll
    for (int nt = 0; nt < 8; ++nt)
#pragma unroll
        for (int j = 0; j < 4; ++j) o[nt][j] = 0.f;
    float m_lo = -1e30f, m_hi = -1e30f, l_lo = 0.f, l_hi = 0.f;

    const int kt_max = 2 * qt + 1;
    for (int kt = 0; kt <= kt_max; ++kt) {
        __syncthreads();
        const int kbase = kt * 64;

#pragma unroll
        for (int i = 0; i < 4; ++i) {
            int r = row0 + i * 16;
            float4 v = *(const float4*)&Kg[(size_t)(kbase + r) * KSTRIDE + kh * D + f4 * 4];
            uint4 u = make_uint4(f2t(v.x), f2t(v.y), f2t(v.z), f2t(v.w));
            *(uint4*)&Ks[r * FP + f4 * 4] = u;
        }
#pragma unroll
        for (int i = 0; i < 4; ++i) {
            int r = row0 + i * 16;
            float4 v = *(const float4*)&Vg[(size_t)(kbase + r) * KSTRIDE + kh * D + f4 * 4];
            Vs[(f4 * 4 + 0) * FP + r] = f2t(v.x);
            Vs[(f4 * 4 + 1) * FP + r] = f2t(v.y);
            Vs[(f4 * 4 + 2) * FP + r] = f2t(v.z);
            Vs[(f4 * 4 + 3) * FP + r] = f2t(v.w);
        }
        __syncthreads();

        const bool active = (kbase <= qbase + m0 + 15);
        if (!active) continue;

        float s[8][4];
#pragma unroll
        for (int nt = 0; nt < 8; ++nt)
#pragma unroll
            for (int j = 0; j < 4; ++j) s[nt][j] = 0.f;

#pragma unroll
        for (int ks = 0; ks < 8; ++ks) {
            const int k0 = ks * 8;
            unsigned a0 = Qs[(m0 + qr) * FP + k0 + qc];
            unsigned a1 = Qs[(m0 + 8 + qr) * FP + k0 + qc];
            unsigned a2 = Qs[(m0 + qr) * FP + k0 + 4 + qc];
            unsigned a3 = Qs[(m0 + 8 + qr) * FP + k0 + 4 + qc];
#pragma unroll
            for (int nt = 0; nt < 8; ++nt) {
                unsigned b0 = Ks[(nt * 8 + qr) * FP + k0 + qc];
                unsigned b1 = Ks[(nt * 8 + qr) * FP + k0 + 4 + qc];
                mma_tf32(s[nt], a0, a1, a2, a3, b0, b1);
            }
        }

        const int q_lo = qbase + m0 + qr;
        const int q_hi = q_lo + 8;
        const bool need_mask = (kbase + 63 > q_lo);
#pragma unroll
        for (int nt = 0; nt < 8; ++nt) {
#pragma unroll
            for (int j = 0; j < 2; ++j) {
                int kcol = kbase + nt * 8 + 2 * qc + j;
                float v0 = s[nt][j] * 0.125f;
                float v1 = s[nt][2 + j] * 0.125f;
                if (need_mask && kcol > q_lo) v0 = -1e30f;
                if (need_mask && kcol > q_hi) v1 = -1e30f;
                s[nt][j] = v0;
                s[nt][2 + j] = v1;
            }
        }

        float tm_lo = -1e30f, tm_hi = -1e30f;
#pragma unroll
        for (int nt = 0; nt < 8; ++nt) {
            tm_lo = fmaxf(tm_lo, fmaxf(s[nt][0], s[nt][1]));
            tm_hi = fmaxf(tm_hi, fmaxf(s[nt][2], s[nt][3]));
        }
#pragma unroll
        for (int off = 1; off <= 2; off <<= 1) {
            tm_lo = fmaxf(tm_lo, __shfl_xor_sync(0xffffffffu, tm_lo, off));
            tm_hi = fmaxf(tm_hi, __shfl_xor_sync(0xffffffffu, tm_hi, off));
        }
        float mn_lo = fmaxf(m_lo, tm_lo);
        float mn_hi = fmaxf(m_hi, tm_hi);
        float fac_lo = __expf(m_lo - mn_lo);
        float fac_hi = __expf(m_hi - mn_hi);

        float sum_lo = 0.f, sum_hi = 0.f;
#pragma unroll
        for (int nt = 0; nt < 8; ++nt) {
            float p0 = __expf(s[nt][0] - mn_lo);
            float p1 = __expf(s[nt][1] - mn_lo);
            float p2 = __expf(s[nt][2] - mn_hi);
            float p3 = __expf(s[nt][3] - mn_hi);
            s[nt][0] = p0; s[nt][1] = p1; s[nt][2] = p2; s[nt][3] = p3;
            sum_lo += p0 + p1;
            sum_hi += p2 + p3;
        }
#pragma unroll
        for (int off = 1; off <= 2; off <<= 1) {
            sum_lo += __shfl_xor_sync(0xffffffffu, sum_lo, off);
            sum_hi += __shfl_xor_sync(0xffffffffu, sum_hi, off);
        }
        l_lo = l_lo * fac_lo + sum_lo;
        l_hi = l_hi * fac_hi + sum_hi;
        m_lo = mn_lo;
        m_hi = mn_hi;

#pragma unroll
        for (int nt = 0; nt < 8; ++nt) {
            o[nt][0] *= fac_lo; o[nt][1] *= fac_lo;
            o[nt][2] *= fac_hi; o[nt][3] *= fac_hi;
        }

#pragma unroll
        for (int nt = 0; nt < 8; ++nt) {
            int r = m0 + qr;
            int c = nt * 8 + 2 * qc;
            Ps[r * FP + c]           = f2t(s[nt][0]);
            Ps[r * FP + c + 1]       = f2t(s[nt][1]);
            Ps[(r + 8) * FP + c]     = f2t(s[nt][2]);
            Ps[(r + 8) * FP + c + 1] = f2t(s[nt][3]);
        }
        __syncwarp();

#pragma unroll
        for (int ks = 0; ks < 8; ++ks) {
            const int k0 = ks * 8;
            unsigned a0 = Ps[(m0 + qr) * FP + k0 + qc];
            unsigned a1 = Ps[(m0 + 8 + qr) * FP + k0 + qc];
            unsigned a2 = Ps[(m0 + qr) * FP + k0 + 4 + qc];
            unsigned a3 = Ps[(m0 + 8 + qr) * FP + k0 + 4 + qc];
#pragma unroll
            for (int nt = 0; nt < 8; ++nt) {
                unsigned b0 = Vs[(nt * 8 + qr) * FP + k0 + qc];
                unsigned b1 = Vs[(nt * 8 + qr) * FP + k0 + 4 + qc];
                mma_tf32(o[nt], a0, a1, a2, a3, b0, b1);
            }
        }
    }

    float inv_lo = 1.f / l_lo;
    float inv_hi = 1.f / l_hi;
#pragma unroll
    for (int nt = 0; nt < 8; ++nt) {
        int row = qbase + m0 + qr;
        int col = h * D + nt * 8 + 2 * qc;
        *(float2*)&O[(size_t)row * QSTRIDE + col] =
            make_float2(o[nt][0] * inv_lo, o[nt][1] * inv_lo);
        *(float2*)&O[(size_t)(row + 8) * QSTRIDE + col] =
            make_float2(o[nt][2] * inv_hi, o[nt][3] * inv_hi);
    }
}

// ---------------- launch ---------------------------------------------------
extern "C" void kernel_launch(void* const* d_in, const int* in_sizes, int n_in,
                              void* d_out, int out_size) {
    const float* x  = (const float*)d_in[0];
    const float* fc = (const float*)d_in[1];
    const float* Wq = (const float*)d_in[3];
    const float* Wk = (const float*)d_in[4];
    const float* Wv = (const float*)d_in[5];
    const float* Wo = (const float*)d_in[6];
    float* out = (float*)d_out;

    float *Q, *K, *V, *A;
    cudaGetSymbolAddress((void**)&Q, g_Q);
    cudaGetSymbolAddress((void**)&K, g_K);
    cudaGetSymbolAddress((void**)&V, g_V);
    cudaGetSymbolAddress((void**)&A, g_A);

    cudaFuncSetAttribute(flash_tc_kernel,
                         cudaFuncAttributeMaxDynamicSharedMemorySize,
                         FA_SMEM_BYTES);

    // fused QKV projection + RoPE
    qkv_gemm_kernel<<<dim3(NTOT / 128, S / 128), 128>>>(x, Wq, Wk, Wv, fc, Q, K, V);

    // causal GQA flash attention
    flash_tc_kernel<<<dim3(S / 128, HQ), 256, FA_SMEM_BYTES>>>(Q, K, V, A);

    // output projection
    tgemm_kernel<<<dim3(E / 128, S / 128), 128>>>(A, Wo, out, S, E, E);
}

// round 6
// speedup vs baseline: 5.2518x; 1.3247x over previous
#include <cuda_runtime.h>
#include <cuda_bf16.h>

// Problem constants
#define S      2048
#define E      2048
#define HQ     32
#define HKV    8
#define D      64
#define QSTRIDE (HQ*D)    // 2048
#define KSTRIDE (HKV*D)   // 512
#define NTOT   (QSTRIDE + 2*KSTRIDE)  // 3072

// ---------------- scratch (device globals; no allocation allowed) ----------
__device__ float g_Q[S * QSTRIDE];
__device__ float g_K[S * KSTRIDE];
__device__ float g_V[S * KSTRIDE];
__device__ float g_A[S * QSTRIDE];

// ---------------- helpers ---------------------------------------------------
__device__ __forceinline__ unsigned f2t(float f) {
    unsigned u;
    asm("cvt.rna.tf32.f32 %0, %1;" : "=r"(u) : "f"(f));
    return u;
}

__device__ __forceinline__ void mma_tf32(float c[4],
                                         unsigned a0, unsigned a1, unsigned a2, unsigned a3,
                                         unsigned b0, unsigned b1) {
    asm volatile(
        "mma.sync.aligned.m16n8k8.row.col.f32.tf32.tf32.f32 "
        "{%0,%1,%2,%3}, {%4,%5,%6,%7}, {%8,%9}, {%0,%1,%2,%3};\n"
        : "+f"(c[0]), "+f"(c[1]), "+f"(c[2]), "+f"(c[3])
        : "r"(a0), "r"(a1), "r"(a2), "r"(a3), "r"(b0), "r"(b1));
}

// GEMM smem geometry: A row-major [128][36], B [32][136], double buffered.
#define AP   36
#define BP   136
#define ASZ  (128 * AP)       // words per A buffer
#define BSZ  (32 * BP)        // words per B buffer
#define GEMM_SMEM_BYTES ((2 * ASZ + 2 * BSZ) * 4)   // 71680

// ============================================================================
// GEMM core: 128 threads / 4 warps, block 128x128, warp tile 64x64
// (mt=4, nt=8), BK=32. Double-buffered smem: store phase for block k+1
// overlaps MMAs of block k; one barrier per k-block.
// ============================================================================
struct GemmCore {
    template <bool ROPE_EPI>
    static __device__ __forceinline__ void run(
        const float* __restrict__ A, const float* __restrict__ B,
        float* __restrict__ C, const float* __restrict__ F,
        int N, int K, int mbase, int nbase_local) {

        extern __shared__ unsigned smg[];
        unsigned* AsBuf = smg;                  // 2 * ASZ
        unsigned* BsBuf = smg + 2 * ASZ;        // 2 * BSZ

        const int tid  = threadIdx.x;
        const int lane = tid & 31;
        const int warp = tid >> 5;
        const int m0w = (warp >> 1) * 64;
        const int n0w = (warp & 1) * 64;
        const int qr = lane >> 2, qc = lane & 3;

        float acc[4][8][4];
#pragma unroll
        for (int mt = 0; mt < 4; ++mt)
#pragma unroll
            for (int nt = 0; nt < 8; ++nt)
#pragma unroll
                for (int j = 0; j < 4; ++j) acc[mt][nt][j] = 0.f;

        const int arow = tid >> 3, af4 = tid & 7;   // A: 16 rows/pass x 8 f4
        const int brow = tid >> 5, bf4 = tid & 31;  // B: 4 rows/pass x 32 f4

        float4 pa[8], pb[8];

        // ---- prologue: block 0 -> buf0, prefetch block 1 ----
#pragma unroll
        for (int i = 0; i < 8; ++i)
            pa[i] = *(const float4*)&A[(size_t)(mbase + arow + i * 16) * K + af4 * 4];
#pragma unroll
        for (int i = 0; i < 8; ++i)
            pb[i] = *(const float4*)&B[(size_t)(brow + i * 4) * N + nbase_local + bf4 * 4];
#pragma unroll
        for (int i = 0; i < 8; ++i) {
            int r = arow + i * 16;
            uint4 u = make_uint4(f2t(pa[i].x), f2t(pa[i].y), f2t(pa[i].z), f2t(pa[i].w));
            *(uint4*)&AsBuf[r * AP + af4 * 4] = u;
        }
#pragma unroll
        for (int i = 0; i < 8; ++i) {
            int r = brow + i * 4;
            uint4 u = make_uint4(f2t(pb[i].x), f2t(pb[i].y), f2t(pb[i].z), f2t(pb[i].w));
            *(uint4*)&BsBuf[r * BP + bf4 * 4] = u;
        }
        if (32 < K) {
#pragma unroll
            for (int i = 0; i < 8; ++i)
                pa[i] = *(const float4*)&A[(size_t)(mbase + arow + i * 16) * K + 32 + af4 * 4];
#pragma unroll
            for (int i = 0; i < 8; ++i)
                pb[i] = *(const float4*)&B[(size_t)(32 + brow + i * 4) * N + nbase_local + bf4 * 4];
        }
        __syncthreads();

        int buf = 0;
        for (int kb = 0; kb < K; kb += 32) {
            unsigned* Asb = AsBuf + buf * ASZ;
            unsigned* Bsb = BsBuf + buf * BSZ;

            // store prefetched block kb+32 into the other buffer
            if (kb + 32 < K) {
                unsigned* Asn = AsBuf + (buf ^ 1) * ASZ;
                unsigned* Bsn = BsBuf + (buf ^ 1) * BSZ;
#pragma unroll
                for (int i = 0; i < 8; ++i) {
                    int r = arow + i * 16;
                    uint4 u = make_uint4(f2t(pa[i].x), f2t(pa[i].y), f2t(pa[i].z), f2t(pa[i].w));
                    *(uint4*)&Asn[r * AP + af4 * 4] = u;
                }
#pragma unroll
                for (int i = 0; i < 8; ++i) {
                    int r = brow + i * 4;
                    uint4 u = make_uint4(f2t(pb[i].x), f2t(pb[i].y), f2t(pb[i].z), f2t(pb[i].w));
                    *(uint4*)&Bsn[r * BP + bf4 * 4] = u;
                }
            }
            // prefetch block kb+64 into registers
            if (kb + 64 < K) {
#pragma unroll
                for (int i = 0; i < 8; ++i)
                    pa[i] = *(const float4*)&A[(size_t)(mbase + arow + i * 16) * K + kb + 64 + af4 * 4];
#pragma unroll
                for (int i = 0; i < 8; ++i)
                    pb[i] = *(const float4*)&B[(size_t)(kb + 64 + brow + i * 4) * N + nbase_local + bf4 * 4];
            }

            // compute on current buffer
#pragma unroll
            for (int ks = 0; ks < 4; ++ks) {
                const int k0 = ks * 8;
                unsigned a[4][4];
#pragma unroll
                for (int mt = 0; mt < 4; ++mt) {
                    int m = m0w + mt * 16;
                    a[mt][0] = Asb[(m + qr) * AP + k0 + qc];
                    a[mt][1] = Asb[(m + 8 + qr) * AP + k0 + qc];
                    a[mt][2] = Asb[(m + qr) * AP + k0 + 4 + qc];
                    a[mt][3] = Asb[(m + 8 + qr) * AP + k0 + 4 + qc];
                }
#pragma unroll
                for (int nt = 0; nt < 8; ++nt) {
                    int n = n0w + nt * 8;
                    unsigned b0 = Bsb[(k0 + qc) * BP + n + qr];
                    unsigned b1 = Bsb[(k0 + 4 + qc) * BP + n + qr];
#pragma unroll
                    for (int mt = 0; mt < 4; ++mt)
                        mma_tf32(acc[mt][nt], a[mt][0], a[mt][1], a[mt][2], a[mt][3], b0, b1);
                }
            }
            __syncthreads();
            buf ^= 1;
        }

        // epilogue (optional fused RoPE; cols in rotation pairs (2c, 2c+1))
#pragma unroll
        for (int mt = 0; mt < 4; ++mt) {
#pragma unroll
            for (int nt = 0; nt < 8; ++nt) {
                int row = mbase + m0w + mt * 16 + qr;
                int lcol = nbase_local + n0w + nt * 8 + 2 * qc;
                float2 v0 = make_float2(acc[mt][nt][0], acc[mt][nt][1]);
                float2 v1 = make_float2(acc[mt][nt][2], acc[mt][nt][3]);
                if (ROPE_EPI) {
                    int d = lcol & 63;
                    float2 f0 = *(const float2*)&F[(size_t)row * 64 + d];
                    float2 f1 = *(const float2*)&F[(size_t)(row + 8) * 64 + d];
                    v0 = make_float2(v0.x * f0.x - v0.y * f0.y, v0.x * f0.y + v0.y * f0.x);
                    v1 = make_float2(v1.x * f1.x - v1.y * f1.y, v1.x * f1.y + v1.y * f1.x);
                }
                *(float2*)&C[(size_t)row * N + lcol] = v0;
                *(float2*)&C[(size_t)(row + 8) * N + lcol] = v1;
            }
        }
    }
};

// ---- fused QKV + RoPE (V does NOT get RoPE) --------------------------------
__global__ __launch_bounds__(128)
void qkv_gemm_kernel(const float* __restrict__ A,
                     const float* __restrict__ Wq,
                     const float* __restrict__ Wk,
                     const float* __restrict__ Wv,
                     const float* __restrict__ F,
                     float* __restrict__ Qp,
                     float* __restrict__ Kp,
                     float* __restrict__ Vp) {
    const int mbase = blockIdx.y * 128;
    const int nbase = blockIdx.x * 128;
    if (nbase < QSTRIDE) {
        GemmCore::run<true>(A, Wq, Qp, F, QSTRIDE, E, mbase, nbase);
    } else if (nbase < QSTRIDE + KSTRIDE) {
        GemmCore::run<true>(A, Wk, Kp, F, KSTRIDE, E, mbase, nbase - QSTRIDE);
    } else {
        GemmCore::run<false>(A, Wv, Vp, nullptr, KSTRIDE, E, mbase,
                             nbase - QSTRIDE - KSTRIDE);   // <-- FIX: no RoPE on V
    }
}

// ---- plain GEMM (output projection) ----------------------------------------
__global__ __launch_bounds__(128)
void tgemm_kernel(const float* __restrict__ A,
                  const float* __restrict__ B,
                  float* __restrict__ C,
                  int M, int N, int K) {
    GemmCore::run<false>(A, B, C, nullptr, N, K, blockIdx.y * 128, blockIdx.x * 128);
}

// ============================================================================
// TF32 flash attention: 128 q-rows/CTA, 4 warps x 32 rows (mt=2, nt=8),
// 128 threads, V row-major, conflict-free pitches.
// ============================================================================
#define FPQ 68    // Q, K, P pitch
#define FPV 72    // V pitch
#define FA_SMEM_WORDS (128*FPQ + 64*FPQ + 64*FPV + 128*FPQ)
#define FA_SMEM_BYTES (FA_SMEM_WORDS * 4)   // 105472

__global__ __launch_bounds__(128)
void flash_tc_kernel(const float* __restrict__ Q,
                     const float* __restrict__ Kg,
                     const float* __restrict__ Vg,
                     float* __restrict__ O) {
    const int h = blockIdx.y;
    const int qt = (gridDim.x - 1) - blockIdx.x;
    const int qbase = qt * 128;
    const int kh = h >> 2;

    extern __shared__ unsigned smu[];
    unsigned* Qs = smu;                          // [128][FPQ]
    unsigned* Ks = Qs + 128 * FPQ;               // [64][FPQ]
    unsigned* Vs = Ks + 64 * FPQ;                // [64][FPV] row-major [k][d]
    unsigned* Ps = Vs + 64 * FPV;                // [128][FPQ]

    const int tid = threadIdx.x;
    const int lane = tid & 31;
    const int warp = tid >> 5;
    const int m0 = warp * 32;
    const int qr = lane >> 2;
    const int qc = lane & 3;

    const int f4 = tid & 15;
    const int row0 = tid >> 4;                   // 0..7

    // load Q tile (128 x 64)
#pragma unroll
    for (int i = 0; i < 16; ++i) {
        int r = row0 + i * 8;
        float4 v = *(const float4*)&Q[(size_t)(qbase + r) * QSTRIDE + h * D + f4 * 4];
        uint4 u = make_uint4(f2t(v.x), f2t(v.y), f2t(v.z), f2t(v.w));
        *(uint4*)&Qs[r * FPQ + f4 * 4] = u;
    }

    float o[2][8][4];
#pragma unroll
    for (int mt = 0; mt < 2; ++mt)
#pragma unroll
        for (int nt = 0; nt < 8; ++nt)
#pragma unroll
            for (int j = 0; j < 4; ++j) o[mt][nt][j] = 0.f;
    float mr[2][2], lr[2][2];
#pragma unroll
    for (int mt = 0; mt < 2; ++mt) {
        mr[mt][0] = -1e30f; mr[mt][1] = -1e30f;
        lr[mt][0] = 0.f;    lr[mt][1] = 0.f;
    }

    const int kt_max = 2 * qt + 1;
    for (int kt = 0; kt <= kt_max; ++kt) {
        __syncthreads();
        const int kbase = kt * 64;

        // load K tile (64 x 64) row-major
#pragma unroll
        for (int i = 0; i < 8; ++i) {
            int r = row0 + i * 8;
            float4 v = *(const float4*)&Kg[(size_t)(kbase + r) * KSTRIDE + kh * D + f4 * 4];
            uint4 u = make_uint4(f2t(v.x), f2t(v.y), f2t(v.z), f2t(v.w));
            *(uint4*)&Ks[r * FPQ + f4 * 4] = u;
        }
        // load V tile (64 x 64) row-major [k][d]
#pragma unroll
        for (int i = 0; i < 8; ++i) {
            int r = row0 + i * 8;
            float4 v = *(const float4*)&Vg[(size_t)(kbase + r) * KSTRIDE + kh * D + f4 * 4];
            uint4 u = make_uint4(f2t(v.x), f2t(v.y), f2t(v.z), f2t(v.w));
            *(uint4*)&Vs[r * FPV + f4 * 4] = u;
        }
        __syncthreads();

        // warps fully below this k tile skip compute
        if (kbase > qbase + m0 + 31) continue;

        // ---- S = Q K^T ----
        float s[2][8][4];
#pragma unroll
        for (int mt = 0; mt < 2; ++mt)
#pragma unroll
            for (int nt = 0; nt < 8; ++nt)
#pragma unroll
                for (int j = 0; j < 4; ++j) s[mt][nt][j] = 0.f;

#pragma unroll
        for (int ks = 0; ks < 8; ++ks) {
            const int k0 = ks * 8;
            unsigned a[2][4];
#pragma unroll
            for (int mt = 0; mt < 2; ++mt) {
                int m = m0 + mt * 16;
                a[mt][0] = Qs[(m + qr) * FPQ + k0 + qc];
                a[mt][1] = Qs[(m + 8 + qr) * FPQ + k0 + qc];
                a[mt][2] = Qs[(m + qr) * FPQ + k0 + 4 + qc];
                a[mt][3] = Qs[(m + 8 + qr) * FPQ + k0 + 4 + qc];
            }
#pragma unroll
            for (int nt = 0; nt < 8; ++nt) {
                unsigned b0 = Ks[(nt * 8 + qr) * FPQ + k0 + qc];
                unsigned b1 = Ks[(nt * 8 + qr) * FPQ + k0 + 4 + qc];
#pragma unroll
                for (int mt = 0; mt < 2; ++mt)
                    mma_tf32(s[mt][nt], a[mt][0], a[mt][1], a[mt][2], a[mt][3], b0, b1);
            }
        }

        // ---- scale + causal mask + online softmax (per mt) ----
#pragma unroll
        for (int mt = 0; mt < 2; ++mt) {
            const int q_lo = qbase + m0 + mt * 16 + qr;
            const int q_hi = q_lo + 8;
            const bool need_mask = (kbase + 63 > q_lo);
#pragma unroll
            for (int nt = 0; nt < 8; ++nt) {
#pragma unroll
                for (int j = 0; j < 2; ++j) {
                    int kcol = kbase + nt * 8 + 2 * qc + j;
                    float v0 = s[mt][nt][j] * 0.125f;
                    float v1 = s[mt][nt][2 + j] * 0.125f;
                    if (need_mask && kcol > q_lo) v0 = -1e30f;
                    if (need_mask && kcol > q_hi) v1 = -1e30f;
                    s[mt][nt][j] = v0;
                    s[mt][nt][2 + j] = v1;
                }
            }

            float tm_lo = -1e30f, tm_hi = -1e30f;
#pragma unroll
            for (int nt = 0; nt < 8; ++nt) {
                tm_lo = fmaxf(tm_lo, fmaxf(s[mt][nt][0], s[mt][nt][1]));
                tm_hi = fmaxf(tm_hi, fmaxf(s[mt][nt][2], s[mt][nt][3]));
            }
#pragma unroll
            for (int off = 1; off <= 2; off <<= 1) {
                tm_lo = fmaxf(tm_lo, __shfl_xor_sync(0xffffffffu, tm_lo, off));
                tm_hi = fmaxf(tm_hi, __shfl_xor_sync(0xffffffffu, tm_hi, off));
            }
            float mn_lo = fmaxf(mr[mt][0], tm_lo);
            float mn_hi = fmaxf(mr[mt][1], tm_hi);
            float fac_lo = __expf(mr[mt][0] - mn_lo);
            float fac_hi = __expf(mr[mt][1] - mn_hi);

            float sum_lo = 0.f, sum_hi = 0.f;
#pragma unroll
            for (int nt = 0; nt < 8; ++nt) {
                float p0 = __expf(s[mt][nt][0] - mn_lo);
                float p1 = __expf(s[mt][nt][1] - mn_lo);
                float p2 = __expf(s[mt][nt][2] - mn_hi);
                float p3 = __expf(s[mt][nt][3] - mn_hi);
                s[mt][nt][0] = p0; s[mt][nt][1] = p1;
                s[mt][nt][2] = p2; s[mt][nt][3] = p3;
                sum_lo += p0 + p1;
                sum_hi += p2 + p3;
            }
#pragma unroll
            for (int off = 1; off <= 2; off <<= 1) {
                sum_lo += __shfl_xor_sync(0xffffffffu, sum_lo, off);
                sum_hi += __shfl_xor_sync(0xffffffffu, sum_hi, off);
            }
            lr[mt][0] = lr[mt][0] * fac_lo + sum_lo;
            lr[mt][1] = lr[mt][1] * fac_hi + sum_hi;
            mr[mt][0] = mn_lo;
            mr[mt][1] = mn_hi;

#pragma unroll
            for (int nt = 0; nt < 8; ++nt) {
                o[mt][nt][0] *= fac_lo; o[mt][nt][1] *= fac_lo;
                o[mt][nt][2] *= fac_hi; o[mt][nt][3] *= fac_hi;
            }

            // write P fragments to smem (warp-private rows)
#pragma unroll
            for (int nt = 0; nt < 8; ++nt) {
                int r = m0 + mt * 16 + qr;
                int c = nt * 8 + 2 * qc;
                Ps[r * FPQ + c]           = f2t(s[mt][nt][0]);
                Ps[r * FPQ + c + 1]       = f2t(s[mt][nt][1]);
                Ps[(r + 8) * FPQ + c]     = f2t(s[mt][nt][2]);
                Ps[(r + 8) * FPQ + c + 1] = f2t(s[mt][nt][3]);
            }
        }
        __syncwarp();

        // ---- O += P V (B-fragments straight from row-major V) ----
#pragma unroll
        for (int ks = 0; ks < 8; ++ks) {
            const int k0 = ks * 8;
            unsigned a[2][4];
#pragma unroll
            for (int mt = 0; mt < 2; ++mt) {
                int m = m0 + mt * 16;
                a[mt][0] = Ps[(m + qr) * FPQ + k0 + qc];
                a[mt][1] = Ps[(m + 8 + qr) * FPQ + k0 + qc];
                a[mt][2] = Ps[(m + qr) * FPQ + k0 + 4 + qc];
                a[mt][3] = Ps[(m + 8 + qr) * FPQ + k0 + 4 + qc];
            }
#pragma unroll
            for (int nt = 0; nt < 8; ++nt) {
                unsigned b0 = Vs[(k0 + qc) * FPV + nt * 8 + qr];
                unsigned b1 = Vs[(k0 + 4 + qc) * FPV + nt * 8 + qr];
#pragma unroll
                for (int mt = 0; mt < 2; ++mt)
                    mma_tf32(o[mt][nt], a[mt][0], a[mt][1], a[mt][2], a[mt][3], b0, b1);
            }
        }
    }

    // ---- normalize + write out ----
#pragma unroll
    for (int mt = 0; mt < 2; ++mt) {
        float inv_lo = 1.f / lr[mt][0];
        float inv_hi = 1.f / lr[mt][1];
#pragma unroll
        for (int nt = 0; nt < 8; ++nt) {
            int row = qbase + m0 + mt * 16 + qr;
            int col = h * D + nt * 8 + 2 * qc;
            *(float2*)&O[(size_t)row * QSTRIDE + col] =
                make_float2(o[mt][nt][0] * inv_lo, o[mt][nt][1] * inv_lo);
            *(float2*)&O[(size_t)(row + 8) * QSTRIDE + col] =
                make_float2(o[mt][nt][2] * inv_hi, o[mt][nt][3] * inv_hi);
        }
    }
}

// ---------------- launch ---------------------------------------------------
extern "C" void kernel_launch(void* const* d_in, const int* in_sizes, int n_in,
                              void* d_out, int out_size) {
    const float* x  = (const float*)d_in[0];
    const float* fc = (const float*)d_in[1];
    const float* Wq = (const float*)d_in[3];
    const float* Wk = (const float*)d_in[4];
    const float* Wv = (const float*)d_in[5];
    const float* Wo = (const float*)d_in[6];
    float* out = (float*)d_out;

    float *Q, *K, *V, *A;
    cudaGetSymbolAddress((void**)&Q, g_Q);
    cudaGetSymbolAddress((void**)&K, g_K);
    cudaGetSymbolAddress((void**)&V, g_V);
    cudaGetSymbolAddress((void**)&A, g_A);

    cudaFuncSetAttribute(qkv_gemm_kernel,
                         cudaFuncAttributeMaxDynamicSharedMemorySize, GEMM_SMEM_BYTES);
    cudaFuncSetAttribute(tgemm_kernel,
                         cudaFuncAttributeMaxDynamicSharedMemorySize, GEMM_SMEM_BYTES);
    cudaFuncSetAttribute(flash_tc_kernel,
                         cudaFuncAttributeMaxDynamicSharedMemorySize, FA_SMEM_BYTES);

    // fused QKV projection + RoPE (Q,K only)
    qkv_gemm_kernel<<<dim3(NTOT / 128, S / 128), 128, GEMM_SMEM_BYTES>>>(
        x, Wq, Wk, Wv, fc, Q, K, V);

    // causal GQA flash attention
    flash_tc_kernel<<<dim3(S / 128, HQ), 128, FA_SMEM_BYTES>>>(Q, K, V, A);

    // output projection
    tgemm_kernel<<<dim3(E / 128, S / 128), 128, GEMM_SMEM_BYTES>>>(A, Wo, out, S, E, E);
}